// round 11
// baseline (speedup 1.0000x reference)
#include <cuda_runtime.h>
#include <cstdint>

// MazeBrain: recurrent adaptive-LIF, T=1200, B=16, N=1024.
// 8 CTAs x 512 threads: each CTA simulates TWO independent batches
// (256 threads x 4 cols each) with separate named barriers, so the two
// instruction streams interleave and fill each other's latency stalls.
// Per batch: dual-parity monotonic spike rings (byte offsets), ballot append,
// 16-deep float4 gather, one named barrier per step.

#define T_STEPS 1200
#define BATCH   16
#define NN      1024
#define WHIST   1000
#define TPB     512

__device__ __forceinline__ void group_bar(int g) {
    // named barrier per 256-thread group (ids 1 and 2)
    asm volatile("bar.sync %0, %1;" :: "r"(g + 1), "r"(256) : "memory");
}

__global__ void __launch_bounds__(TPB, 1)
mazebrain_kernel(const float* __restrict__ Iext,   // [T,B,N]
                 const float* __restrict__ W,      // [N,N]
                 float* __restrict__ out)          // [2,T,B,N]: spikes, potentials
{
    const int tid  = threadIdx.x;
    const int g    = tid >> 8;          // batch slot within CTA: 0 or 1
    const int gtid = tid & 255;         // thread id within group
    const int lane = tid & 31;
    const int b    = blockIdx.x * 2 + g;
    const int m0   = gtid * 4;

    __shared__ int s_list[2][2][NN];    // [group][parity][entry] = j*4096 byte offsets
    __shared__ int s_cnt[2][2];         // [group][parity] monotonic counters

    if (tid < 4) ((int*)s_cnt)[tid] = 0;
    __syncthreads();

    float v[4], adapt[4], thr[4], rsum[4];
    int   refr[4];
#pragma unroll
    for (int k = 0; k < 4; k++) {
        v[k] = -65.0f; adapt[k] = 0.0f; thr[k] = -55.0f; rsum[k] = 0.0f; refr[k] = 0;
    }
    int consumed[2] = {0, 0};

    float* __restrict__ spikes_out = out;
    float* __restrict__ pot_out    = out + (size_t)T_STEPS * BATCH * NN;
    const size_t stride = (size_t)BATCH * NN;
    const char* __restrict__ Wb = (const char*)(W + m0);

    size_t ob = (size_t)b * NN + m0;
    float4 Ie_next   = __ldg((const float4*)(Iext + ob));
    float4 hist_next = make_float4(0.f, 0.f, 0.f, 0.f);

    for (int t = 0; t < T_STEPS; t++) {
        const int p = t & 1;            // append parity
        const int q = p ^ 1;            // consume parity
        const float4 Ie   = Ie_next;
        const float4 hist = hist_next;

        // ---- sparse gather of previous step's spikes (byte-offset entries)
        const int e = s_cnt[g][q];
        int i = consumed[q];
        int n = e - i;
        consumed[q] = e;
        const int* __restrict__ lst = s_list[g][q];

        float a0 = Ie.x, a1 = Ie.y, a2 = Ie.z, a3 = Ie.w;
        while (n >= 16) {
            int o[16];
#pragma unroll
            for (int k = 0; k < 16; k++) o[k] = lst[(i + k) & (NN - 1)];
            float4 r[16];
#pragma unroll
            for (int k = 0; k < 16; k++) r[k] = *(const float4*)(Wb + o[k]);
#pragma unroll
            for (int k = 0; k < 16; k++) {
                a0 += r[k].x; a1 += r[k].y; a2 += r[k].z; a3 += r[k].w;
            }
            i += 16; n -= 16;
        }
        if (n >= 8) {
            int o[8];
#pragma unroll
            for (int k = 0; k < 8; k++) o[k] = lst[(i + k) & (NN - 1)];
            float4 r[8];
#pragma unroll
            for (int k = 0; k < 8; k++) r[k] = *(const float4*)(Wb + o[k]);
#pragma unroll
            for (int k = 0; k < 8; k++) {
                a0 += r[k].x; a1 += r[k].y; a2 += r[k].z; a3 += r[k].w;
            }
            i += 8; n -= 8;
        }
        if (n >= 4) {
            int o[4];
#pragma unroll
            for (int k = 0; k < 4; k++) o[k] = lst[(i + k) & (NN - 1)];
            float4 r[4];
#pragma unroll
            for (int k = 0; k < 4; k++) r[k] = *(const float4*)(Wb + o[k]);
#pragma unroll
            for (int k = 0; k < 4; k++) {
                a0 += r[k].x; a1 += r[k].y; a2 += r[k].z; a3 += r[k].w;
            }
            i += 4; n -= 4;
        }
        while (n > 0) {
            float4 r = *(const float4*)(Wb + lst[i & (NN - 1)]);
            a0 += r.x; a1 += r.y; a2 += r.z; a3 += r.w;
            i++; n--;
        }
        float Iin[4] = {a0, a1, a2, a3};

        // ---- neuron update (integrate -> fire/reset -> adapt -> homeo)
        float spk[4], vout[4];
        bool  fired[4];
#pragma unroll
        for (int k = 0; k < 4; k++) {
            bool  active = (refr[k] <= 0);
            float v_int  = 0.9f * (v[k] + 65.0f) - 65.0f + Iin[k] - adapt[k];
            float v1     = active ? v_int : v[k];
            int   r1     = active ? refr[k] : (refr[k] - 1);
            fired[k] = (v1 >= thr[k]);
            spk[k]  = fired[k] ? 1.0f : 0.0f;
            v[k]    = fired[k] ? -70.0f : v1;
            vout[k] = v[k];
            adapt[k] = (fired[k] ? (adapt[k] + 0.2f) : adapt[k]) * 0.95f;
            refr[k]  = fired[k] ? 5 : r1;
        }

        // ---- warp-aggregated append: 4 ballots, 1 atomic per warp, byte offsets
        uint32_t b0 = __ballot_sync(0xffffffffu, fired[0]);
        uint32_t b1 = __ballot_sync(0xffffffffu, fired[1]);
        uint32_t b2 = __ballot_sync(0xffffffffu, fired[2]);
        uint32_t b3 = __ballot_sync(0xffffffffu, fired[3]);
        const int c0 = __popc(b0), c1 = __popc(b1), c2 = __popc(b2), c3 = __popc(b3);
        const int wtot = c0 + c1 + c2 + c3;
        if (wtot) {
            int base = 0;
            if (lane == 0) base = atomicAdd(&s_cnt[g][p], wtot);
            base = __shfl_sync(0xffffffffu, base, 0);
            const uint32_t lt = (1u << lane) - 1u;
            int* __restrict__ wl = s_list[g][p];
            if (fired[0]) wl[(base + __popc(b0 & lt)) & (NN - 1)] = m0 << 12;
            if (fired[1]) wl[(base + c0 + __popc(b1 & lt)) & (NN - 1)] = (m0 + 1) << 12;
            if (fired[2]) wl[(base + c0 + c1 + __popc(b2 & lt)) & (NN - 1)] = (m0 + 2) << 12;
            if (fired[3]) wl[(base + c0 + c1 + c2 + __popc(b3 & lt)) & (NN - 1)] = (m0 + 3) << 12;
        }

        // ---- outputs (spikes region doubles as the homeostatic history ring)
        *(float4*)(spikes_out + ob) = make_float4(spk[0], spk[1], spk[2], spk[3]);
        *(float4*)(pot_out    + ob) = make_float4(vout[0], vout[1], vout[2], vout[3]);

        // ---- homeostatic sliding-window rate
        rsum[0] += spk[0] - hist.x; rsum[1] += spk[1] - hist.y;
        rsum[2] += spk[2] - hist.z; rsum[3] += spk[3] - hist.w;
        if (t + 1 >= WHIST) {
#pragma unroll
            for (int k = 0; k < 4; k++) {
                float ta = thr[k] + 0.001f * (rsum[k] * (1.0f / WHIST) - 0.01f);
                thr[k] = fminf(fmaxf(ta, 0.1f), 5.0f);
            }
        }

        // ---- prefetch next step's inputs
        const size_t ob_next = ob + stride;
        if (t + 1 < T_STEPS) {
            Ie_next = __ldg((const float4*)(Iext + ob_next));
            hist_next = (t + 1 >= WHIST)
                      ? *(const float4*)(spikes_out + (ob_next - (size_t)WHIST * stride))
                      : make_float4(0.f, 0.f, 0.f, 0.f);
        }
        ob = ob_next;

        group_bar(g);   // per-group barrier: orders append(t) before gather(t+1)
    }
}

extern "C" void kernel_launch(void* const* d_in, const int* in_sizes, int n_in,
                              void* d_out, int out_size)
{
    const float* input_current = (const float*)d_in[0];  // [T,B,N]
    const float* W_rec         = (const float*)d_in[1];  // [N,N]
    float* out                 = (float*)d_out;          // [2,T,B,N]
    (void)in_sizes; (void)n_in; (void)out_size;

    mazebrain_kernel<<<BATCH / 2, TPB>>>(input_current, W_rec, out);
}

// round 12
// speedup vs baseline: 1.0668x; 1.0668x over previous
#include <cuda_runtime.h>
#include <cstdint>

// MazeBrain: recurrent adaptive-LIF, T=1200, B=16, N=1024.
// One CTA per batch, 1024 threads, ONE column per thread (32 warps -> max
// latency interleaving, all accesses coalesced). Dual-parity monotonic spike
// rings (byte-offset entries), ballot-aggregated append, 16-deep gather,
// ONE barrier per step.

#define T_STEPS 1200
#define BATCH   16
#define NN      1024
#define WHIST   1000
#define TPB     1024    // thread owns neuron tid

__global__ void __launch_bounds__(TPB, 1)
mazebrain_kernel(const float* __restrict__ Iext,   // [T,B,N]
                 const float* __restrict__ W,      // [N,N]
                 float* __restrict__ out)          // [2,T,B,N]: spikes, potentials
{
    const int b    = blockIdx.x;
    const int tid  = threadIdx.x;
    const int lane = tid & 31;

    __shared__ int s_list[2][NN];   // per-parity ring: entries are j*4096 (byte offsets)
    __shared__ int s_cnt[2];        // per-parity monotonic counters

    if (tid == 0) { s_cnt[0] = 0; s_cnt[1] = 0; }
    __syncthreads();

    float v = -65.0f, adapt = 0.0f, thr = -55.0f, rsum = 0.0f;
    int   refr = 0;
    int   consumed[2] = {0, 0};

    float* __restrict__ spikes_out = out;
    float* __restrict__ pot_out    = out + (size_t)T_STEPS * BATCH * NN;
    const size_t stride = (size_t)BATCH * NN;
    const char* __restrict__ Wb = (const char*)(W + tid);   // this thread's column

    size_t ob = (size_t)b * NN + tid;
    float Ie_next   = __ldg(Iext + ob);
    float hist_next = 0.0f;

    for (int t = 0; t < T_STEPS; t++) {
        const int p = t & 1;        // append parity
        const int q = p ^ 1;        // consume parity
        const float Ie   = Ie_next;
        const float hist = hist_next;

        // ---- sparse gather of previous step's spikes (byte-offset entries)
        const int e = s_cnt[q];
        int i = consumed[q];
        int n = e - i;
        consumed[q] = e;
        const int* __restrict__ lst = s_list[q];

        float a0 = Ie;
        float a1 = 0.0f;            // second accumulator halves the FADD chain
        while (n >= 16) {
            int o[16];
#pragma unroll
            for (int k = 0; k < 16; k++) o[k] = lst[(i + k) & (NN - 1)];
            float r[16];
#pragma unroll
            for (int k = 0; k < 16; k++) r[k] = *(const float*)(Wb + o[k]);
#pragma unroll
            for (int k = 0; k < 8; k++) { a0 += r[2 * k]; a1 += r[2 * k + 1]; }
            i += 16; n -= 16;
        }
        if (n >= 8) {
            int o[8];
#pragma unroll
            for (int k = 0; k < 8; k++) o[k] = lst[(i + k) & (NN - 1)];
            float r[8];
#pragma unroll
            for (int k = 0; k < 8; k++) r[k] = *(const float*)(Wb + o[k]);
#pragma unroll
            for (int k = 0; k < 4; k++) { a0 += r[2 * k]; a1 += r[2 * k + 1]; }
            i += 8; n -= 8;
        }
        if (n >= 4) {
            int o[4];
#pragma unroll
            for (int k = 0; k < 4; k++) o[k] = lst[(i + k) & (NN - 1)];
            float r[4];
#pragma unroll
            for (int k = 0; k < 4; k++) r[k] = *(const float*)(Wb + o[k]);
            a0 += r[0]; a1 += r[1]; a0 += r[2]; a1 += r[3];
            i += 4; n -= 4;
        }
        while (n > 0) {
            a0 += *(const float*)(Wb + lst[i & (NN - 1)]);
            i++; n--;
        }
        const float Iin = a0 + a1;

        // ---- neuron update (integrate -> fire/reset -> adapt -> homeo)
        const bool  active = (refr <= 0);
        const float v_int  = 0.9f * (v + 65.0f) - 65.0f + Iin - adapt;
        const float v1     = active ? v_int : v;
        const int   r1     = active ? refr : (refr - 1);
        const bool  fired  = (v1 >= thr);
        const float sp     = fired ? 1.0f : 0.0f;
        v     = fired ? -70.0f : v1;
        adapt = (fired ? (adapt + 0.2f) : adapt) * 0.95f;
        refr  = fired ? 5 : r1;

        // ---- outputs first (fire-and-forget STGs issue early)
        spikes_out[ob] = sp;
        pot_out[ob]    = v;

        // ---- warp-aggregated append: 1 ballot, 1 atomic per warp, byte offsets
        const uint32_t bm = __ballot_sync(0xffffffffu, fired);
        const int wtot = __popc(bm);
        if (wtot) {
            int base = 0;
            if (lane == 0) base = atomicAdd(&s_cnt[p], wtot);
            base = __shfl_sync(0xffffffffu, base, 0);
            if (fired) {
                const int off = __popc(bm & ((1u << lane) - 1u));
                s_list[p][(base + off) & (NN - 1)] = tid << 12;
            }
        }

        // ---- homeostatic sliding-window rate
        rsum += sp - hist;
        if (t + 1 >= WHIST) {
            thr = fminf(fmaxf(thr + 0.001f * (rsum * (1.0f / WHIST) - 0.01f), 0.1f), 5.0f);
        }

        // ---- prefetch next step's inputs
        const size_t ob_next = ob + stride;
        if (t + 1 < T_STEPS) {
            Ie_next = __ldg(Iext + ob_next);
            hist_next = (t + 1 >= WHIST)
                      ? spikes_out[ob_next - (size_t)WHIST * stride] : 0.0f;
        }
        ob = ob_next;

        __syncthreads();   // orders append(t) before gather(t+1)
    }
}

extern "C" void kernel_launch(void* const* d_in, const int* in_sizes, int n_in,
                              void* d_out, int out_size)
{
    const float* input_current = (const float*)d_in[0];  // [T,B,N]
    const float* W_rec         = (const float*)d_in[1];  // [N,N]
    float* out                 = (float*)d_out;          // [2,T,B,N]
    (void)in_sizes; (void)n_in; (void)out_size;

    mazebrain_kernel<<<BATCH, TPB>>>(input_current, W_rec, out);
}

// round 14
// speedup vs baseline: 1.2710x; 1.1913x over previous
#include <cuda_runtime.h>
#include <cstdint>

// MazeBrain: recurrent adaptive-LIF, T=1200, B=16, N=1024.
// One CTA per batch, 512 threads x 2 cols. Dual-parity monotonic spike rings
// (byte-offset entries), ONE barrier per step. Gather latency-optimized:
// 32-deep first round, 16-deep loop, single MASKED 16-slot tail round
// (ring is zero-initialized so stale entries are always safe W offsets).

#define T_STEPS 1200
#define BATCH   16
#define NN      1024
#define WHIST   1000
#define TPB     512     // thread owns neurons 2*tid, 2*tid+1

__global__ void __launch_bounds__(TPB, 1)
mazebrain_kernel(const float* __restrict__ Iext,   // [T,B,N]
                 const float* __restrict__ W,      // [N,N]
                 float* __restrict__ out)          // [2,T,B,N]: spikes, potentials
{
    const int b   = blockIdx.x;
    const int tid = threadIdx.x;
    const int m0  = tid * 2;

    __shared__ int s_list[2][NN];   // per-parity ring: entries are j*4096 (byte offsets)
    __shared__ int s_cnt[2];        // per-parity monotonic counters

    // zero-init rings so masked tail loads of stale slots are always in-bounds
    for (int idx = tid; idx < 2 * NN; idx += TPB)
        ((int*)s_list)[idx] = 0;
    if (tid == 0) { s_cnt[0] = 0; s_cnt[1] = 0; }
    __syncthreads();

    float v0 = -65.f, v1 = -65.f, ad0 = 0.f, ad1 = 0.f;
    float th0 = -55.f, th1 = -55.f, rs0 = 0.f, rs1 = 0.f;
    int   rf0 = 0, rf1 = 0;
    int   consumed[2] = {0, 0};

    float* __restrict__ spikes_out = out;
    float* __restrict__ pot_out    = out + (size_t)T_STEPS * BATCH * NN;
    const size_t stride = (size_t)BATCH * NN;
    const char* __restrict__ Wb = (const char*)(W + m0);

    size_t ob = (size_t)b * NN + m0;
    float2 Ie_next   = __ldg((const float2*)(Iext + ob));
    float2 hist_next = make_float2(0.f, 0.f);

    for (int t = 0; t < T_STEPS; t++) {
        const int p = t & 1;        // append parity
        const int q = p ^ 1;        // consume parity
        const float2 Ie   = Ie_next;
        const float2 hist = hist_next;

        // ---- sparse gather of previous step's spikes (byte-offset entries)
        const int e = s_cnt[q];
        int i = consumed[q];
        int n = e - i;
        consumed[q] = e;
        const int* __restrict__ lst = s_list[q];

        float a0 = Ie.x, a1 = Ie.y;

        // round 1: 32 loads in one flight
        if (n >= 32) {
            int o[32];
#pragma unroll
            for (int k = 0; k < 32; k++) o[k] = lst[(i + k) & (NN - 1)];
            float2 r[32];
#pragma unroll
            for (int k = 0; k < 32; k++) r[k] = *(const float2*)(Wb + o[k]);
#pragma unroll
            for (int k = 0; k < 32; k++) { a0 += r[k].x; a1 += r[k].y; }
            i += 32; n -= 32;
        }
        // 16-deep loop for the middle
        while (n >= 16) {
            int o[16];
#pragma unroll
            for (int k = 0; k < 16; k++) o[k] = lst[(i + k) & (NN - 1)];
            float2 r[16];
#pragma unroll
            for (int k = 0; k < 16; k++) r[k] = *(const float2*)(Wb + o[k]);
#pragma unroll
            for (int k = 0; k < 16; k++) { a0 += r[k].x; a1 += r[k].y; }
            i += 16; n -= 16;
        }
        // single masked tail round (stale entries are valid offsets; adds predicated)
        if (n > 0) {
            int o[16];
#pragma unroll
            for (int k = 0; k < 16; k++) o[k] = lst[(i + k) & (NN - 1)];
            float2 r[16];
#pragma unroll
            for (int k = 0; k < 16; k++) r[k] = *(const float2*)(Wb + o[k]);
#pragma unroll
            for (int k = 0; k < 16; k++) {
                if (k < n) { a0 += r[k].x; a1 += r[k].y; }
            }
        }

        // ---- neuron update (integrate -> fire/reset -> adapt -> homeo)
        const bool  act0 = (rf0 <= 0), act1 = (rf1 <= 0);
        const float vi0  = 0.9f * (v0 + 65.0f) - 65.0f + a0 - ad0;
        const float vi1  = 0.9f * (v1 + 65.0f) - 65.0f + a1 - ad1;
        const float v10  = act0 ? vi0 : v0;
        const float v11  = act1 ? vi1 : v1;
        const int   r10  = act0 ? rf0 : (rf0 - 1);
        const int   r11  = act1 ? rf1 : (rf1 - 1);
        const bool  f0   = (v10 >= th0);
        const bool  f1   = (v11 >= th1);
        const float sp0  = f0 ? 1.0f : 0.0f;
        const float sp1  = f1 ? 1.0f : 0.0f;
        v0 = f0 ? -70.0f : v10;
        v1 = f1 ? -70.0f : v11;
        ad0 = (f0 ? (ad0 + 0.2f) : ad0) * 0.95f;
        ad1 = (f1 ? (ad1 + 0.2f) : ad1) * 0.95f;
        rf0 = f0 ? 5 : r10;
        rf1 = f1 ? 5 : r11;

        // ---- distributed append (byte offsets j*4096; ptxas REDUX-aggregates)
        if (f0) {
            int idx = atomicAdd(&s_cnt[p], 1);
            s_list[p][idx & (NN - 1)] = m0 << 12;
        }
        if (f1) {
            int idx = atomicAdd(&s_cnt[p], 1);
            s_list[p][idx & (NN - 1)] = (m0 + 1) << 12;
        }

        // ---- outputs (spikes region doubles as the homeostatic history ring)
        *(float2*)(spikes_out + ob) = make_float2(sp0, sp1);
        *(float2*)(pot_out    + ob) = make_float2(v0, v1);

        // ---- homeostatic sliding-window rate
        rs0 += sp0 - hist.x;
        rs1 += sp1 - hist.y;
        if (t + 1 >= WHIST) {
            th0 = fminf(fmaxf(th0 + 0.001f * (rs0 * (1.0f / WHIST) - 0.01f), 0.1f), 5.0f);
            th1 = fminf(fmaxf(th1 + 0.001f * (rs1 * (1.0f / WHIST) - 0.01f), 0.1f), 5.0f);
        }

        // ---- prefetch next step's inputs
        const size_t ob_next = ob + stride;
        if (t + 1 < T_STEPS) {
            Ie_next = __ldg((const float2*)(Iext + ob_next));
            hist_next = (t + 1 >= WHIST)
                      ? *(const float2*)(spikes_out + (ob_next - (size_t)WHIST * stride))
                      : make_float2(0.f, 0.f);
        }
        ob = ob_next;

        __syncthreads();   // orders append(t) before gather(t+1)
    }
}

extern "C" void kernel_launch(void* const* d_in, const int* in_sizes, int n_in,
                              void* d_out, int out_size)
{
    const float* input_current = (const float*)d_in[0];  // [T,B,N]
    const float* W_rec         = (const float*)d_in[1];  // [N,N]
    float* out                 = (float*)d_out;          // [2,T,B,N]
    (void)in_sizes; (void)n_in; (void)out_size;

    mazebrain_kernel<<<BATCH, TPB>>>(input_current, W_rec, out);
}

// round 15
// speedup vs baseline: 1.3173x; 1.0365x over previous
#include <cuda_runtime.h>
#include <cstdint>

// MazeBrain: recurrent adaptive-LIF, T=1200, B=16, N=1024.
// One CTA per batch, 512 threads x 2 cols. Dual-parity monotonic spike rings
// (byte-offset entries), ONE barrier per step. Gather latency-optimized:
// unmasked 32-deep rounds, then ONE masked round (32-slot if n>=16, else
// 16-slot) — stale ring entries are valid W offsets, adds are predicated.
// Typical step: 1-2 serial L2 round-trips total.

#define T_STEPS 1200
#define BATCH   16
#define NN      1024
#define WHIST   1000
#define TPB     512     // thread owns neurons 2*tid, 2*tid+1

__global__ void __launch_bounds__(TPB, 1)
mazebrain_kernel(const float* __restrict__ Iext,   // [T,B,N]
                 const float* __restrict__ W,      // [N,N]
                 float* __restrict__ out)          // [2,T,B,N]: spikes, potentials
{
    const int b   = blockIdx.x;
    const int tid = threadIdx.x;
    const int m0  = tid * 2;

    __shared__ int s_list[2][NN];   // per-parity ring: entries are j*4096 (byte offsets)
    __shared__ int s_cnt[2];        // per-parity monotonic counters

    // zero-init rings so masked loads of stale slots are always in-bounds
    for (int idx = tid; idx < 2 * NN; idx += TPB)
        ((int*)s_list)[idx] = 0;
    if (tid == 0) { s_cnt[0] = 0; s_cnt[1] = 0; }
    __syncthreads();

    float v0 = -65.f, v1 = -65.f, ad0 = 0.f, ad1 = 0.f;
    float th0 = -55.f, th1 = -55.f, rs0 = 0.f, rs1 = 0.f;
    int   rf0 = 0, rf1 = 0;
    int   consumed[2] = {0, 0};

    float* __restrict__ spikes_out = out;
    float* __restrict__ pot_out    = out + (size_t)T_STEPS * BATCH * NN;
    const size_t stride = (size_t)BATCH * NN;
    const char* __restrict__ Wb = (const char*)(W + m0);

    size_t ob = (size_t)b * NN + m0;
    float2 Ie_next   = __ldg((const float2*)(Iext + ob));
    float2 hist_next = make_float2(0.f, 0.f);

    for (int t = 0; t < T_STEPS; t++) {
        const int p = t & 1;        // append parity
        const int q = p ^ 1;        // consume parity
        const float2 Ie   = Ie_next;
        const float2 hist = hist_next;

        // ---- sparse gather of previous step's spikes (byte-offset entries)
        const int e = s_cnt[q];
        int i = consumed[q];
        int n = e - i;
        consumed[q] = e;
        const int* __restrict__ lst = s_list[q];

        float a0 = Ie.x, a1 = Ie.y;

        // unmasked 32-deep rounds
        while (n >= 32) {
            int o[32];
#pragma unroll
            for (int k = 0; k < 32; k++) o[k] = lst[(i + k) & (NN - 1)];
            float2 r[32];
#pragma unroll
            for (int k = 0; k < 32; k++) r[k] = *(const float2*)(Wb + o[k]);
#pragma unroll
            for (int k = 0; k < 32; k++) { a0 += r[k].x; a1 += r[k].y; }
            i += 32; n -= 32;
        }
        // ONE masked tail round: 32-slot if n>=16, else 16-slot
        if (n >= 16) {
            int o[32];
#pragma unroll
            for (int k = 0; k < 32; k++) o[k] = lst[(i + k) & (NN - 1)];
            float2 r[32];
#pragma unroll
            for (int k = 0; k < 32; k++) r[k] = *(const float2*)(Wb + o[k]);
#pragma unroll
            for (int k = 0; k < 32; k++) {
                if (k < n) { a0 += r[k].x; a1 += r[k].y; }
            }
        } else if (n > 0) {
            int o[16];
#pragma unroll
            for (int k = 0; k < 16; k++) o[k] = lst[(i + k) & (NN - 1)];
            float2 r[16];
#pragma unroll
            for (int k = 0; k < 16; k++) r[k] = *(const float2*)(Wb + o[k]);
#pragma unroll
            for (int k = 0; k < 16; k++) {
                if (k < n) { a0 += r[k].x; a1 += r[k].y; }
            }
        }

        // ---- neuron update (integrate -> fire/reset -> adapt -> homeo)
        const bool  act0 = (rf0 <= 0), act1 = (rf1 <= 0);
        const float vi0  = 0.9f * (v0 + 65.0f) - 65.0f + a0 - ad0;
        const float vi1  = 0.9f * (v1 + 65.0f) - 65.0f + a1 - ad1;
        const float v10  = act0 ? vi0 : v0;
        const float v11  = act1 ? vi1 : v1;
        const int   r10  = act0 ? rf0 : (rf0 - 1);
        const int   r11  = act1 ? rf1 : (rf1 - 1);
        const bool  f0   = (v10 >= th0);
        const bool  f1   = (v11 >= th1);
        const float sp0  = f0 ? 1.0f : 0.0f;
        const float sp1  = f1 ? 1.0f : 0.0f;
        v0 = f0 ? -70.0f : v10;
        v1 = f1 ? -70.0f : v11;
        ad0 = (f0 ? (ad0 + 0.2f) : ad0) * 0.95f;
        ad1 = (f1 ? (ad1 + 0.2f) : ad1) * 0.95f;
        rf0 = f0 ? 5 : r10;
        rf1 = f1 ? 5 : r11;

        // ---- distributed append (byte offsets j*4096; ptxas REDUX-aggregates)
        if (f0) {
            int idx = atomicAdd(&s_cnt[p], 1);
            s_list[p][idx & (NN - 1)] = m0 << 12;
        }
        if (f1) {
            int idx = atomicAdd(&s_cnt[p], 1);
            s_list[p][idx & (NN - 1)] = (m0 + 1) << 12;
        }

        // ---- outputs (spikes region doubles as the homeostatic history ring)
        *(float2*)(spikes_out + ob) = make_float2(sp0, sp1);
        *(float2*)(pot_out    + ob) = make_float2(v0, v1);

        // ---- homeostatic sliding-window rate
        rs0 += sp0 - hist.x;
        rs1 += sp1 - hist.y;
        if (t + 1 >= WHIST) {
            th0 = fminf(fmaxf(th0 + 0.001f * (rs0 * (1.0f / WHIST) - 0.01f), 0.1f), 5.0f);
            th1 = fminf(fmaxf(th1 + 0.001f * (rs1 * (1.0f / WHIST) - 0.01f), 0.1f), 5.0f);
        }

        // ---- prefetch next step's inputs
        const size_t ob_next = ob + stride;
        if (t + 1 < T_STEPS) {
            Ie_next = __ldg((const float2*)(Iext + ob_next));
            hist_next = (t + 1 >= WHIST)
                      ? *(const float2*)(spikes_out + (ob_next - (size_t)WHIST * stride))
                      : make_float2(0.f, 0.f);
        }
        ob = ob_next;

        __syncthreads();   // orders append(t) before gather(t+1)
    }
}

extern "C" void kernel_launch(void* const* d_in, const int* in_sizes, int n_in,
                              void* d_out, int out_size)
{
    const float* input_current = (const float*)d_in[0];  // [T,B,N]
    const float* W_rec         = (const float*)d_in[1];  // [N,N]
    float* out                 = (float*)d_out;          // [2,T,B,N]
    (void)in_sizes; (void)n_in; (void)out_size;

    mazebrain_kernel<<<BATCH, TPB>>>(input_current, W_rec, out);
}

// round 17
// speedup vs baseline: 1.3651x; 1.0363x over previous
#include <cuda_runtime.h>
#include <cstdint>

// MazeBrain: recurrent adaptive-LIF, T=1200, B=16, N=1024.
// One CTA per batch, 512 threads x 2 cols. FOUR-phase spike lists:
// step t appends to slot t&3, consumes slot (t-1)&3, resets slot (t+1)&3
// (last touched 2 barriers ago -> race-free reset with ONE barrier/step).
// Lists start at 0 each epoch: int4-aligned offset loads, no ring masking
// on append. Packed add.rn.f32x2 accumulation. Unmasked 32-deep rounds +
// ONE masked tail round (32- or 16-slot; stale entries are valid offsets).

#define T_STEPS 1200
#define BATCH   16
#define NN      1024
#define WHIST   1000
#define TPB     512     // thread owns neurons 2*tid, 2*tid+1

__device__ __forceinline__ void addx2(unsigned long long& acc, unsigned long long val) {
    asm("add.rn.f32x2 %0, %0, %1;" : "+l"(acc) : "l"(val));
}

__global__ void __launch_bounds__(TPB, 1)
mazebrain_kernel(const float* __restrict__ Iext,   // [T,B,N]
                 const float* __restrict__ W,      // [N,N]
                 float* __restrict__ out)          // [2,T,B,N]: spikes, potentials
{
    const int b   = blockIdx.x;
    const int tid = threadIdx.x;
    const int m0  = tid * 2;

    __shared__ __align__(16) int s_list[4][NN];  // 4-phase lists: entries j*4096 (byte offsets)
    __shared__ int s_cnt[4];                     // 4-phase counters

    // zero-init lists (masked stale loads must see valid offsets) + counters
    for (int idx = tid; idx < 4 * NN; idx += TPB)
        ((int*)s_list)[idx] = 0;
    if (tid < 4) s_cnt[tid] = 0;
    __syncthreads();

    float v0 = -65.f, v1 = -65.f, ad0 = 0.f, ad1 = 0.f;
    float th0 = -55.f, th1 = -55.f, rs0 = 0.f, rs1 = 0.f;
    int   rf0 = 0, rf1 = 0;

    float* __restrict__ spikes_out = out;
    float* __restrict__ pot_out    = out + (size_t)T_STEPS * BATCH * NN;
    const size_t stride = (size_t)BATCH * NN;
    const char* __restrict__ Wb = (const char*)(W + m0);

    size_t ob = (size_t)b * NN + m0;
    float2 Ie_next   = __ldg((const float2*)(Iext + ob));
    float2 hist_next = make_float2(0.f, 0.f);

    for (int t = 0; t < T_STEPS; t++) {
        const int a = t & 3;            // append slot (this step's spikes)
        const int c = (t + 3) & 3;      // consume slot (previous step's spikes)
        const int z = (t + 1) & 3;      // reset slot (appended next step;
                                        // last consumed 2 barriers ago)
        if (tid == 0) s_cnt[z] = 0;

        const float2 Ie   = Ie_next;
        const float2 hist = hist_next;

        // ---- sparse gather of previous step's spikes (byte-offset entries)
        int n = s_cnt[c];
        const int* __restrict__ lst = s_list[c];
        int i4 = 0;                     // int4 index (i/4); i stays 32-aligned

        unsigned long long acc0, acc1;
        asm("mov.b64 %0, {%1, %2};" : "=l"(acc0) : "f"(Ie.x), "f"(Ie.y));
        acc1 = 0ull;                    // (0.0f, 0.0f)

        // unmasked 32-deep rounds
        while (n >= 32) {
            int4 o4[8];
#pragma unroll
            for (int k = 0; k < 8; k++) o4[k] = ((const int4*)lst)[i4 + k];
            unsigned long long r[32];
#pragma unroll
            for (int k = 0; k < 8; k++) {
                r[4 * k + 0] = *(const unsigned long long*)(Wb + o4[k].x);
                r[4 * k + 1] = *(const unsigned long long*)(Wb + o4[k].y);
                r[4 * k + 2] = *(const unsigned long long*)(Wb + o4[k].z);
                r[4 * k + 3] = *(const unsigned long long*)(Wb + o4[k].w);
            }
#pragma unroll
            for (int k = 0; k < 16; k++) {
                addx2(acc0, r[2 * k]);
                addx2(acc1, r[2 * k + 1]);
            }
            i4 += 8; n -= 32;
        }
        // ONE masked tail round: 32-slot if n>=16, else 16-slot
        if (n >= 16) {
            int4 o4[8];
#pragma unroll
            for (int k = 0; k < 8; k++) o4[k] = ((const int4*)lst)[i4 + k];
            unsigned long long r[32];
#pragma unroll
            for (int k = 0; k < 8; k++) {
                r[4 * k + 0] = *(const unsigned long long*)(Wb + o4[k].x);
                r[4 * k + 1] = *(const unsigned long long*)(Wb + o4[k].y);
                r[4 * k + 2] = *(const unsigned long long*)(Wb + o4[k].z);
                r[4 * k + 3] = *(const unsigned long long*)(Wb + o4[k].w);
            }
#pragma unroll
            for (int k = 0; k < 32; k++) {
                if (k < n) {
                    if (k & 1) addx2(acc1, r[k]); else addx2(acc0, r[k]);
                }
            }
        } else if (n > 0) {
            int4 o4[4];
#pragma unroll
            for (int k = 0; k < 4; k++) o4[k] = ((const int4*)lst)[i4 + k];
            unsigned long long r[16];
#pragma unroll
            for (int k = 0; k < 4; k++) {
                r[4 * k + 0] = *(const unsigned long long*)(Wb + o4[k].x);
                r[4 * k + 1] = *(const unsigned long long*)(Wb + o4[k].y);
                r[4 * k + 2] = *(const unsigned long long*)(Wb + o4[k].z);
                r[4 * k + 3] = *(const unsigned long long*)(Wb + o4[k].w);
            }
#pragma unroll
            for (int k = 0; k < 16; k++) {
                if (k < n) {
                    if (k & 1) addx2(acc1, r[k]); else addx2(acc0, r[k]);
                }
            }
        }

        float x0, y0, x1, y1;
        asm("mov.b64 {%0, %1}, %2;" : "=f"(x0), "=f"(y0) : "l"(acc0));
        asm("mov.b64 {%0, %1}, %2;" : "=f"(x1), "=f"(y1) : "l"(acc1));
        const float a0 = x0 + x1;
        const float a1 = y0 + y1;

        // ---- neuron update (integrate -> fire/reset -> adapt -> homeo)
        const bool  act0 = (rf0 <= 0), act1 = (rf1 <= 0);
        const float vi0  = 0.9f * (v0 + 65.0f) - 65.0f + a0 - ad0;
        const float vi1  = 0.9f * (v1 + 65.0f) - 65.0f + a1 - ad1;
        const float v10  = act0 ? vi0 : v0;
        const float v11  = act1 ? vi1 : v1;
        const int   r10  = act0 ? rf0 : (rf0 - 1);
        const int   r11  = act1 ? rf1 : (rf1 - 1);
        const bool  f0   = (v10 >= th0);
        const bool  f1   = (v11 >= th1);
        const float sp0  = f0 ? 1.0f : 0.0f;
        const float sp1  = f1 ? 1.0f : 0.0f;
        v0 = f0 ? -70.0f : v10;
        v1 = f1 ? -70.0f : v11;
        ad0 = (f0 ? (ad0 + 0.2f) : ad0) * 0.95f;
        ad1 = (f1 ? (ad1 + 0.2f) : ad1) * 0.95f;
        rf0 = f0 ? 5 : r10;
        rf1 = f1 ? 5 : r11;

        // ---- distributed append (counter freshly zeroed -> idx < NN always)
        if (f0) {
            int idx = atomicAdd(&s_cnt[a], 1);
            s_list[a][idx] = m0 << 12;
        }
        if (f1) {
            int idx = atomicAdd(&s_cnt[a], 1);
            s_list[a][idx] = (m0 + 1) << 12;
        }

        // ---- outputs (spikes region doubles as the homeostatic history ring)
        *(float2*)(spikes_out + ob) = make_float2(sp0, sp1);
        *(float2*)(pot_out    + ob) = make_float2(v0, v1);

        // ---- homeostatic sliding-window rate
        rs0 += sp0 - hist.x;
        rs1 += sp1 - hist.y;
        if (t + 1 >= WHIST) {
            th0 = fminf(fmaxf(th0 + 0.001f * (rs0 * (1.0f / WHIST) - 0.01f), 0.1f), 5.0f);
            th1 = fminf(fmaxf(th1 + 0.001f * (rs1 * (1.0f / WHIST) - 0.01f), 0.1f), 5.0f);
        }

        // ---- prefetch next step's inputs
        const size_t ob_next = ob + stride;
        if (t + 1 < T_STEPS) {
            Ie_next = __ldg((const float2*)(Iext + ob_next));
            hist_next = (t + 1 >= WHIST)
                      ? *(const float2*)(spikes_out + (ob_next - (size_t)WHIST * stride))
                      : make_float2(0.f, 0.f);
        }
        ob = ob_next;

        __syncthreads();   // orders append(t) before gather(t+1) and reset(t+1)
    }
}

extern "C" void kernel_launch(void* const* d_in, const int* in_sizes, int n_in,
                              void* d_out, int out_size)
{
    const float* input_current = (const float*)d_in[0];  // [T,B,N]
    const float* W_rec         = (const float*)d_in[1];  // [N,N]
    float* out                 = (float*)d_out;          // [2,T,B,N]
    (void)in_sizes; (void)n_in; (void)out_size;

    mazebrain_kernel<<<BATCH, TPB>>>(input_current, W_rec, out);
}